// round 1
// baseline (speedup 1.0000x reference)
#include <cuda_runtime.h>
#include <math.h>

#define BATCH 4
#define SEQ   4096
#define DM    512
#define MROWS (BATCH*SEQ)

// Scratch (device globals: allocation-free per harness rules). 4 x 32MB.
__device__ float g_q[MROWS*DM];
__device__ float g_k[MROWS*DM];
__device__ float g_v[MROWS*DM];
__device__ float g_ctx[MROWS*DM];

// ---------------------------------------------------------------------------
// GEMM: C[M,N] = A[M,512] @ W[N,512]^T   (both row-major, K contiguous)
// 64x64 tile, BK=32, 256 threads, 4x4 microtile, transposed smem tiles.
// ---------------------------------------------------------------------------
#define BM  64
#define BN  64
#define BKK 32

__device__ __forceinline__ void gemm_body(const float* __restrict__ A,
                                          const float* __restrict__ W,
                                          float* __restrict__ C) {
    __shared__ float sA[BKK][BM + 4];   // [k][m], pad 4 keeps float4 alignment
    __shared__ float sB[BKK][BN + 4];   // [k][n]
    const int m0 = blockIdx.y * BM;
    const int n0 = blockIdx.x * BN;
    const int t  = threadIdx.x;
    const int tx = t & 15;
    const int ty = t >> 4;

    float acc[4][4];
    #pragma unroll
    for (int i = 0; i < 4; i++)
        #pragma unroll
        for (int j = 0; j < 4; j++) acc[i][j] = 0.f;

    for (int k0 = 0; k0 < DM; k0 += BKK) {
        #pragma unroll
        for (int i = 0; i < 8; i++) {
            int e = t + i * 256;          // 2048 elements per tile
            int k = e & 31;
            int m = e >> 5;
            sA[k][m] = A[(size_t)(m0 + m) * DM + k0 + k];
            sB[k][m] = W[(size_t)(n0 + m) * DM + k0 + k];
        }
        __syncthreads();

        #pragma unroll 8
        for (int kk = 0; kk < BKK; kk++) {
            float4 a = *(const float4*)&sA[kk][ty * 4];
            float4 b = *(const float4*)&sB[kk][tx * 4];
            acc[0][0] += a.x * b.x; acc[0][1] += a.x * b.y; acc[0][2] += a.x * b.z; acc[0][3] += a.x * b.w;
            acc[1][0] += a.y * b.x; acc[1][1] += a.y * b.y; acc[1][2] += a.y * b.z; acc[1][3] += a.y * b.w;
            acc[2][0] += a.z * b.x; acc[2][1] += a.z * b.y; acc[2][2] += a.z * b.z; acc[2][3] += a.z * b.w;
            acc[3][0] += a.w * b.x; acc[3][1] += a.w * b.y; acc[3][2] += a.w * b.z; acc[3][3] += a.w * b.w;
        }
        __syncthreads();
    }

    #pragma unroll
    for (int i = 0; i < 4; i++) {
        float4 o = make_float4(acc[i][0], acc[i][1], acc[i][2], acc[i][3]);
        *(float4*)&C[(size_t)(m0 + ty * 4 + i) * DM + n0 + tx * 4] = o;
    }
}

__global__ void __launch_bounds__(256, 1)
qkv_proj(const float* __restrict__ x,
         const float* __restrict__ Wq,
         const float* __restrict__ Wk,
         const float* __restrict__ Wv) {
    const float* W;
    float* C;
    if (blockIdx.z == 0)      { W = Wq; C = g_q; }
    else if (blockIdx.z == 1) { W = Wk; C = g_k; }
    else                      { W = Wv; C = g_v; }
    gemm_body(x, W, C);
}

__global__ void __launch_bounds__(256, 1)
out_proj(const float* __restrict__ Wo, float* __restrict__ out) {
    gemm_body(g_ctx, Wo, out);
}

// ---------------------------------------------------------------------------
// Causal flash attention, fp32. 32 queries x 32 keys per step, D=512.
// 256 threads. QK^T: warp w owns rows w*4..w*4+3, lane = key column.
// PV: thread owns (row = t>>3, 64 d-columns at (t&7)*64), acc in registers.
// ---------------------------------------------------------------------------
#define SQ_F   (32 * 512)
#define SKT_F  (512 * 33)
#define SV_F   (32 * 512)
#define SS_F   (32 * 32)
#define ATTN_SMEM_FLOATS (SQ_F + SKT_F + SV_F + SS_F + 96)
#define ATTN_SMEM_BYTES  (ATTN_SMEM_FLOATS * 4)

__global__ void __launch_bounds__(256, 1) attn_kernel() {
    extern __shared__ float sh[];
    float* sQ  = sh;                 // [32][512], pre-scaled by 1/sqrt(D)
    float* sKt = sQ  + SQ_F;         // [512][33]  (K transposed, pad 33)
    float* sV  = sKt + SKT_F;        // [32][512]
    float* sS  = sV  + SV_F;         // [32][32]   probabilities
    float* sM  = sS  + SS_F;         // [32] running max
    float* sL  = sM  + 32;           // [32] running sum
    float* sAl = sL  + 32;           // [32] per-step rescale

    const int b    = blockIdx.y;
    const int qt   = gridDim.x - 1 - blockIdx.x;   // longest-first scheduling
    const int q0   = qt * 32;
    const int t    = threadIdx.x;
    const int lane = t & 31;
    const int w    = t >> 5;
    const float scale = 0.04419417382415922f;      // 1/sqrt(512)

    // Load + pre-scale Q tile
    const float* Qg = g_q + ((size_t)b * SEQ + q0) * DM;
    #pragma unroll
    for (int i = 0; i < 16; i++) {
        int e  = t + i * 256;          // float4 index, 4096 total
        int r  = e >> 7;
        int dq = e & 127;
        float4 v = *(const float4*)&Qg[r * DM + dq * 4];
        v.x *= scale; v.y *= scale; v.z *= scale; v.w *= scale;
        *(float4*)&sQ[r * DM + dq * 4] = v;
    }
    if (t < 32) { sM[t] = -INFINITY; sL[t] = 0.f; }

    float acc[64];
    #pragma unroll
    for (int c = 0; c < 64; c++) acc[c] = 0.f;

    const int i_row = t >> 3;
    const int co    = (t & 7) * 64;
    const int r0    = w * 4;

    __syncthreads();

    for (int kt = 0; kt <= qt; kt++) {
        const int k0 = kt * 32;
        const float* Kg = g_k + ((size_t)b * SEQ + k0) * DM;
        const float* Vg = g_v + ((size_t)b * SEQ + k0) * DM;

        // Load K (transposed into sKt) and V
        #pragma unroll
        for (int i = 0; i < 16; i++) {
            int e  = t + i * 256;
            int r  = e >> 7;
            int dq = e & 127;
            int d  = dq * 4;
            float4 kv = *(const float4*)&Kg[r * DM + d];
            sKt[(d + 0) * 33 + r] = kv.x;
            sKt[(d + 1) * 33 + r] = kv.y;
            sKt[(d + 2) * 33 + r] = kv.z;
            sKt[(d + 3) * 33 + r] = kv.w;
            float4 vv = *(const float4*)&Vg[r * DM + d];
            *(float4*)&sV[r * DM + d] = vv;
        }
        __syncthreads();

        // ---- S = Q K^T (each lane: 4 rows x 1 col) ----
        float s0 = 0.f, s1 = 0.f, s2 = 0.f, s3 = 0.f;
        #pragma unroll 8
        for (int d = 0; d < DM; d += 4) {
            float ka = sKt[(d + 0) * 33 + lane];
            float kb = sKt[(d + 1) * 33 + lane];
            float kc = sKt[(d + 2) * 33 + lane];
            float kd = sKt[(d + 3) * 33 + lane];
            float4 qa = *(const float4*)&sQ[(r0 + 0) * DM + d];
            s0 += qa.x * ka + qa.y * kb + qa.z * kc + qa.w * kd;
            float4 qb = *(const float4*)&sQ[(r0 + 1) * DM + d];
            s1 += qb.x * ka + qb.y * kb + qb.z * kc + qb.w * kd;
            float4 qc = *(const float4*)&sQ[(r0 + 2) * DM + d];
            s2 += qc.x * ka + qc.y * kb + qc.z * kc + qc.w * kd;
            float4 qd = *(const float4*)&sQ[(r0 + 3) * DM + d];
            s3 += qd.x * ka + qd.y * kb + qd.z * kc + qd.w * kd;
        }

        // ---- online softmax per row (row values live across lanes) ----
        float sv[4] = { s0, s1, s2, s3 };
        const bool diag = (kt == qt);
        #pragma unroll
        for (int rr = 0; rr < 4; rr++) {
            float s = sv[rr];
            if (diag && (k0 + lane > q0 + r0 + rr)) s = -INFINITY;
            float mx = s;
            #pragma unroll
            for (int off = 16; off; off >>= 1)
                mx = fmaxf(mx, __shfl_xor_sync(0xffffffffu, mx, off));
            float mold = sM[r0 + rr];
            float mnew = fmaxf(mold, mx);
            float p = __expf(s - mnew);
            float psum = p;
            #pragma unroll
            for (int off = 16; off; off >>= 1)
                psum += __shfl_xor_sync(0xffffffffu, psum, off);
            float alpha = __expf(mold - mnew);
            if (lane == 0) {
                sM[r0 + rr]  = mnew;
                sL[r0 + rr]  = sL[r0 + rr] * alpha + psum;
                sAl[r0 + rr] = alpha;
            }
            sS[(r0 + rr) * 32 + lane] = p;
        }
        __syncthreads();

        // ---- O = alpha*O + P V ----
        float al = sAl[i_row];
        #pragma unroll
        for (int c = 0; c < 64; c++) acc[c] *= al;
        const float* srow = &sS[i_row * 32];
        #pragma unroll 2
        for (int j = 0; j < 32; j++) {
            float p = srow[j];
            const float* vrow = &sV[j * DM + co];
            #pragma unroll
            for (int c = 0; c < 64; c += 4) {
                float4 v = *(const float4*)&vrow[c];
                acc[c + 0] += p * v.x;
                acc[c + 1] += p * v.y;
                acc[c + 2] += p * v.z;
                acc[c + 3] += p * v.w;
            }
        }
        __syncthreads();
    }

    // Normalize and write context
    float linv = 1.0f / sL[i_row];
    float* Og = g_ctx + ((size_t)b * SEQ + q0 + i_row) * DM + co;
    #pragma unroll
    for (int c = 0; c < 64; c += 4) {
        float4 o = make_float4(acc[c] * linv, acc[c + 1] * linv,
                               acc[c + 2] * linv, acc[c + 3] * linv);
        *(float4*)&Og[c] = o;
    }
}

// ---------------------------------------------------------------------------
extern "C" void kernel_launch(void* const* d_in, const int* in_sizes, int n_in,
                              void* d_out, int out_size) {
    (void)in_sizes; (void)n_in; (void)out_size;
    const float* x  = (const float*)d_in[0];
    const float* Wq = (const float*)d_in[1];
    const float* Wk = (const float*)d_in[2];
    const float* Wv = (const float*)d_in[3];
    const float* Wo = (const float*)d_in[4];
    float* out = (float*)d_out;

    qkv_proj<<<dim3(DM / BN, MROWS / BM, 3), 256>>>(x, Wq, Wk, Wv);

    cudaFuncSetAttribute(attn_kernel,
                         cudaFuncAttributeMaxDynamicSharedMemorySize,
                         ATTN_SMEM_BYTES);
    attn_kernel<<<dim3(SEQ / 32, BATCH), 256, ATTN_SMEM_BYTES>>>();

    out_proj<<<dim3(DM / BN, MROWS / BM), 256>>>(Wo, out);
}

// round 2
// speedup vs baseline: 4.3510x; 4.3510x over previous
#include <cuda_runtime.h>
#include <math.h>

#define BATCH 4
#define SEQ   4096
#define DM    512
#define MROWS (BATCH*SEQ)

// Scratch (device globals: allocation-free per harness rules). 4 x 32MB.
__device__ float g_q[MROWS*DM];
__device__ float g_k[MROWS*DM];
__device__ float g_v[MROWS*DM];
__device__ float g_ctx[MROWS*DM];

// ---------------------------------------------------------------------------
// GEMM: C[M,N] = A[M,512] @ W[N,512]^T   (both row-major, K contiguous)
// 64x64 tile, BK=32, 256 threads, 4x4 microtile, transposed smem tiles.
// ---------------------------------------------------------------------------
#define BM  64
#define BN  64
#define BKK 32

__device__ __forceinline__ void gemm_body(const float* __restrict__ A,
                                          const float* __restrict__ W,
                                          float* __restrict__ C) {
    __shared__ float sA[BKK][BM + 4];
    __shared__ float sB[BKK][BN + 4];
    const int m0 = blockIdx.y * BM;
    const int n0 = blockIdx.x * BN;
    const int t  = threadIdx.x;
    const int tx = t & 15;
    const int ty = t >> 4;

    float acc[4][4];
    #pragma unroll
    for (int i = 0; i < 4; i++)
        #pragma unroll
        for (int j = 0; j < 4; j++) acc[i][j] = 0.f;

    for (int k0 = 0; k0 < DM; k0 += BKK) {
        #pragma unroll
        for (int i = 0; i < 8; i++) {
            int e = t + i * 256;
            int k = e & 31;
            int m = e >> 5;
            sA[k][m] = A[(size_t)(m0 + m) * DM + k0 + k];
            sB[k][m] = W[(size_t)(n0 + m) * DM + k0 + k];
        }
        __syncthreads();

        #pragma unroll 8
        for (int kk = 0; kk < BKK; kk++) {
            float4 a = *(const float4*)&sA[kk][ty * 4];
            float4 b = *(const float4*)&sB[kk][tx * 4];
            acc[0][0] += a.x * b.x; acc[0][1] += a.x * b.y; acc[0][2] += a.x * b.z; acc[0][3] += a.x * b.w;
            acc[1][0] += a.y * b.x; acc[1][1] += a.y * b.y; acc[1][2] += a.y * b.z; acc[1][3] += a.y * b.w;
            acc[2][0] += a.z * b.x; acc[2][1] += a.z * b.y; acc[2][2] += a.z * b.z; acc[2][3] += a.z * b.w;
            acc[3][0] += a.w * b.x; acc[3][1] += a.w * b.y; acc[3][2] += a.w * b.z; acc[3][3] += a.w * b.w;
        }
        __syncthreads();
    }

    #pragma unroll
    for (int i = 0; i < 4; i++) {
        float4 o = make_float4(acc[i][0], acc[i][1], acc[i][2], acc[i][3]);
        *(float4*)&C[(size_t)(m0 + ty * 4 + i) * DM + n0 + tx * 4] = o;
    }
}

__global__ void __launch_bounds__(256, 1)
qkv_proj(const float* __restrict__ x,
         const float* __restrict__ Wq,
         const float* __restrict__ Wk,
         const float* __restrict__ Wv) {
    const float* W;
    float* C;
    if (blockIdx.z == 0)      { W = Wq; C = g_q; }
    else if (blockIdx.z == 1) { W = Wk; C = g_k; }
    else                      { W = Wv; C = g_v; }
    gemm_body(x, W, C);
}

__global__ void __launch_bounds__(256, 1)
out_proj(const float* __restrict__ Wo, float* __restrict__ out) {
    gemm_body(g_ctx, Wo, out);
}

// ---------------------------------------------------------------------------
// Causal flash attention, fp32. 32 queries x 32 keys per step, D=512.
// 256 threads.
//   QK^T : warp w owns rows 4w..4w+3, lane = key column (unchanged).
//   PV   : warp w owns q-rows (w&3)*8..+7, cols (w>>2)*256 + lane*8..+7.
//          8x8 register microtile -> V read ONCE per 8 q-rows, conflict-free
//          coalesced LDS.128 (lanes consecutive 32B).
// ---------------------------------------------------------------------------
#define SQ_F   (32 * 512)
#define SKT_F  (512 * 33)
#define SV_F   (32 * 512)
#define SS_F   (32 * 32)
#define ATTN_SMEM_FLOATS (SQ_F + SKT_F + SV_F + SS_F + 96)
#define ATTN_SMEM_BYTES  (ATTN_SMEM_FLOATS * 4)

__global__ void __launch_bounds__(256, 1) attn_kernel() {
    extern __shared__ float sh[];
    float* sQ  = sh;                 // [32][512], pre-scaled by 1/sqrt(D)
    float* sKt = sQ  + SQ_F;         // [512][33]  (K transposed, pad 33)
    float* sV  = sKt + SKT_F;        // [32][512]
    float* sS  = sV  + SV_F;         // [32][32]   probabilities
    float* sM  = sS  + SS_F;         // [32] running max
    float* sL  = sM  + 32;           // [32] running sum
    float* sAl = sL  + 32;           // [32] per-step rescale

    const int b    = blockIdx.y;
    const int qt   = gridDim.x - 1 - blockIdx.x;   // longest-first scheduling
    const int q0   = qt * 32;
    const int t    = threadIdx.x;
    const int lane = t & 31;
    const int w    = t >> 5;
    const float scale = 0.04419417382415922f;      // 1/sqrt(512)

    // Load + pre-scale Q tile
    const float* Qg = g_q + ((size_t)b * SEQ + q0) * DM;
    #pragma unroll
    for (int i = 0; i < 16; i++) {
        int e  = t + i * 256;
        int r  = e >> 7;
        int dq = e & 127;
        float4 v = *(const float4*)&Qg[r * DM + dq * 4];
        v.x *= scale; v.y *= scale; v.z *= scale; v.w *= scale;
        *(float4*)&sQ[r * DM + dq * 4] = v;
    }
    if (t < 32) { sM[t] = -INFINITY; sL[t] = 0.f; }

    // PV microtile assignment: 8 rows x 8 cols per thread
    const int pr0   = (w & 3) * 8;               // base q-row for PV
    const int pc0   = (w >> 2) * 256 + lane * 8; // base col  for PV
    const int r0    = w * 4;                     // QK rows

    float acc[8][8];
    #pragma unroll
    for (int r = 0; r < 8; r++)
        #pragma unroll
        for (int c = 0; c < 8; c++) acc[r][c] = 0.f;

    __syncthreads();

    for (int kt = 0; kt <= qt; kt++) {
        const int k0 = kt * 32;
        const float* Kg = g_k + ((size_t)b * SEQ + k0) * DM;
        const float* Vg = g_v + ((size_t)b * SEQ + k0) * DM;

        // Load K (transposed into sKt) and V
        #pragma unroll
        for (int i = 0; i < 16; i++) {
            int e  = t + i * 256;
            int r  = e >> 7;
            int dq = e & 127;
            int d  = dq * 4;
            float4 kv = *(const float4*)&Kg[r * DM + d];
            sKt[(d + 0) * 33 + r] = kv.x;
            sKt[(d + 1) * 33 + r] = kv.y;
            sKt[(d + 2) * 33 + r] = kv.z;
            sKt[(d + 3) * 33 + r] = kv.w;
            float4 vv = *(const float4*)&Vg[r * DM + d];
            *(float4*)&sV[r * DM + d] = vv;
        }
        __syncthreads();

        // ---- S = Q K^T (each lane: 4 rows x 1 col) ----
        float s0 = 0.f, s1 = 0.f, s2 = 0.f, s3 = 0.f;
        #pragma unroll 8
        for (int d = 0; d < DM; d += 4) {
            float ka = sKt[(d + 0) * 33 + lane];
            float kb = sKt[(d + 1) * 33 + lane];
            float kc = sKt[(d + 2) * 33 + lane];
            float kd = sKt[(d + 3) * 33 + lane];
            float4 qa = *(const float4*)&sQ[(r0 + 0) * DM + d];
            s0 += qa.x * ka + qa.y * kb + qa.z * kc + qa.w * kd;
            float4 qb = *(const float4*)&sQ[(r0 + 1) * DM + d];
            s1 += qb.x * ka + qb.y * kb + qb.z * kc + qb.w * kd;
            float4 qc = *(const float4*)&sQ[(r0 + 2) * DM + d];
            s2 += qc.x * ka + qc.y * kb + qc.z * kc + qc.w * kd;
            float4 qd = *(const float4*)&sQ[(r0 + 3) * DM + d];
            s3 += qd.x * ka + qd.y * kb + qd.z * kc + qd.w * kd;
        }

        // ---- online softmax per row (row values live across lanes) ----
        float sv[4] = { s0, s1, s2, s3 };
        const bool diag = (kt == qt);
        #pragma unroll
        for (int rr = 0; rr < 4; rr++) {
            float s = sv[rr];
            if (diag && (k0 + lane > q0 + r0 + rr)) s = -INFINITY;
            float mx = s;
            #pragma unroll
            for (int off = 16; off; off >>= 1)
                mx = fmaxf(mx, __shfl_xor_sync(0xffffffffu, mx, off));
            float mold = sM[r0 + rr];
            float mnew = fmaxf(mold, mx);
            float p = __expf(s - mnew);
            float psum = p;
            #pragma unroll
            for (int off = 16; off; off >>= 1)
                psum += __shfl_xor_sync(0xffffffffu, psum, off);
            float alpha = __expf(mold - mnew);
            if (lane == 0) {
                sM[r0 + rr]  = mnew;
                sL[r0 + rr]  = sL[r0 + rr] * alpha + psum;
                sAl[r0 + rr] = alpha;
            }
            sS[(r0 + rr) * 32 + lane] = p;
        }
        __syncthreads();

        // ---- O = alpha*O + P V  (8x8 register microtile) ----
        #pragma unroll
        for (int r = 0; r < 8; r++) {
            float al = sAl[pr0 + r];
            #pragma unroll
            for (int c = 0; c < 8; c++) acc[r][c] *= al;
        }
        #pragma unroll 4
        for (int j = 0; j < 32; j++) {
            float4 v0 = *(const float4*)&sV[j * DM + pc0];
            float4 v1 = *(const float4*)&sV[j * DM + pc0 + 4];
            #pragma unroll
            for (int r = 0; r < 8; r++) {
                float p = sS[(pr0 + r) * 32 + j];
                acc[r][0] += p * v0.x;
                acc[r][1] += p * v0.y;
                acc[r][2] += p * v0.z;
                acc[r][3] += p * v0.w;
                acc[r][4] += p * v1.x;
                acc[r][5] += p * v1.y;
                acc[r][6] += p * v1.z;
                acc[r][7] += p * v1.w;
            }
        }
        __syncthreads();
    }

    // Normalize and write context
    #pragma unroll
    for (int r = 0; r < 8; r++) {
        float linv = 1.0f / sL[pr0 + r];
        float* Og = g_ctx + ((size_t)b * SEQ + q0 + pr0 + r) * DM + pc0;
        float4 o0 = make_float4(acc[r][0] * linv, acc[r][1] * linv,
                                acc[r][2] * linv, acc[r][3] * linv);
        float4 o1 = make_float4(acc[r][4] * linv, acc[r][5] * linv,
                                acc[r][6] * linv, acc[r][7] * linv);
        *(float4*)&Og[0] = o0;
        *(float4*)&Og[4] = o1;
    }
}

// ---------------------------------------------------------------------------
extern "C" void kernel_launch(void* const* d_in, const int* in_sizes, int n_in,
                              void* d_out, int out_size) {
    (void)in_sizes; (void)n_in; (void)out_size;
    const float* x  = (const float*)d_in[0];
    const float* Wq = (const float*)d_in[1];
    const float* Wk = (const float*)d_in[2];
    const float* Wv = (const float*)d_in[3];
    const float* Wo = (const float*)d_in[4];
    float* out = (float*)d_out;

    qkv_proj<<<dim3(DM / BN, MROWS / BM, 3), 256>>>(x, Wq, Wk, Wv);

    cudaFuncSetAttribute(attn_kernel,
                         cudaFuncAttributeMaxDynamicSharedMemorySize,
                         ATTN_SMEM_BYTES);
    attn_kernel<<<dim3(SEQ / 32, BATCH), 256, ATTN_SMEM_BYTES>>>();

    out_proj<<<dim3(DM / BN, MROWS / BM), 256>>>(Wo, out);
}

// round 3
// speedup vs baseline: 4.3523x; 1.0003x over previous
#include <cuda_runtime.h>
#include <math.h>

#define BATCH 4
#define SEQ   4096
#define DM    512
#define MROWS (BATCH*SEQ)

// Scratch (device globals: allocation-free per harness rules). 4 x 32MB.
__device__ float g_q[MROWS*DM];
__device__ float g_k[MROWS*DM];
__device__ float g_v[MROWS*DM];
__device__ float g_ctx[MROWS*DM];

// ---------------------------------------------------------------------------
// GEMM: C[M,N] = A[M,512] @ W[N,512]^T   (both row-major, K contiguous)
// 64x64 tile, BK=32, 256 threads, 4x4 microtile, transposed smem tiles.
// ---------------------------------------------------------------------------
#define BM  64
#define BN  64
#define BKK 32

__device__ __forceinline__ void gemm_body(const float* __restrict__ A,
                                          const float* __restrict__ W,
                                          float* __restrict__ C) {
    __shared__ float sA[BKK][BM + 4];
    __shared__ float sB[BKK][BN + 4];
    const int m0 = blockIdx.y * BM;
    const int n0 = blockIdx.x * BN;
    const int t  = threadIdx.x;
    const int tx = t & 15;
    const int ty = t >> 4;

    float acc[4][4];
    #pragma unroll
    for (int i = 0; i < 4; i++)
        #pragma unroll
        for (int j = 0; j < 4; j++) acc[i][j] = 0.f;

    for (int k0 = 0; k0 < DM; k0 += BKK) {
        #pragma unroll
        for (int i = 0; i < 8; i++) {
            int e = t + i * 256;
            int k = e & 31;
            int m = e >> 5;
            sA[k][m] = A[(size_t)(m0 + m) * DM + k0 + k];
            sB[k][m] = W[(size_t)(n0 + m) * DM + k0 + k];
        }
        __syncthreads();

        #pragma unroll 8
        for (int kk = 0; kk < BKK; kk++) {
            float4 a = *(const float4*)&sA[kk][ty * 4];
            float4 b = *(const float4*)&sB[kk][tx * 4];
            acc[0][0] += a.x * b.x; acc[0][1] += a.x * b.y; acc[0][2] += a.x * b.z; acc[0][3] += a.x * b.w;
            acc[1][0] += a.y * b.x; acc[1][1] += a.y * b.y; acc[1][2] += a.y * b.z; acc[1][3] += a.y * b.w;
            acc[2][0] += a.z * b.x; acc[2][1] += a.z * b.y; acc[2][2] += a.z * b.z; acc[2][3] += a.z * b.w;
            acc[3][0] += a.w * b.x; acc[3][1] += a.w * b.y; acc[3][2] += a.w * b.z; acc[3][3] += a.w * b.w;
        }
        __syncthreads();
    }

    #pragma unroll
    for (int i = 0; i < 4; i++) {
        float4 o = make_float4(acc[i][0], acc[i][1], acc[i][2], acc[i][3]);
        *(float4*)&C[(size_t)(m0 + ty * 4 + i) * DM + n0 + tx * 4] = o;
    }
}

__global__ void __launch_bounds__(256, 1)
qkv_proj(const float* __restrict__ x,
         const float* __restrict__ Wq,
         const float* __restrict__ Wk,
         const float* __restrict__ Wv) {
    const float* W;
    float* C;
    if (blockIdx.z == 0)      { W = Wq; C = g_q; }
    else if (blockIdx.z == 1) { W = Wk; C = g_k; }
    else                      { W = Wv; C = g_v; }
    gemm_body(x, W, C);
}

__global__ void __launch_bounds__(256, 1)
out_proj(const float* __restrict__ Wo, float* __restrict__ out) {
    gemm_body(g_ctx, Wo, out);
}

// ---------------------------------------------------------------------------
// Causal flash attention, fp32. 32 queries x 32 keys per step, D=512.
// 256 threads.
//   QK^T : warp w owns rows 4w..4w+3, lane = key column (unchanged).
//   PV   : warp w owns q-rows (w&3)*8..+7, cols (w>>2)*256 + lane*8..+7.
//          8x8 register microtile -> V read ONCE per 8 q-rows, conflict-free
//          coalesced LDS.128 (lanes consecutive 32B).
// ---------------------------------------------------------------------------
#define SQ_F   (32 * 512)
#define SKT_F  (512 * 33)
#define SV_F   (32 * 512)
#define SS_F   (32 * 32)
#define ATTN_SMEM_FLOATS (SQ_F + SKT_F + SV_F + SS_F + 96)
#define ATTN_SMEM_BYTES  (ATTN_SMEM_FLOATS * 4)

__global__ void __launch_bounds__(256, 1) attn_kernel() {
    extern __shared__ float sh[];
    float* sQ  = sh;                 // [32][512], pre-scaled by 1/sqrt(D)
    float* sKt = sQ  + SQ_F;         // [512][33]  (K transposed, pad 33)
    float* sV  = sKt + SKT_F;        // [32][512]
    float* sS  = sV  + SV_F;         // [32][32]   probabilities
    float* sM  = sS  + SS_F;         // [32] running max
    float* sL  = sM  + 32;           // [32] running sum
    float* sAl = sL  + 32;           // [32] per-step rescale

    const int b    = blockIdx.y;
    const int qt   = gridDim.x - 1 - blockIdx.x;   // longest-first scheduling
    const int q0   = qt * 32;
    const int t    = threadIdx.x;
    const int lane = t & 31;
    const int w    = t >> 5;
    const float scale = 0.04419417382415922f;      // 1/sqrt(512)

    // Load + pre-scale Q tile
    const float* Qg = g_q + ((size_t)b * SEQ + q0) * DM;
    #pragma unroll
    for (int i = 0; i < 16; i++) {
        int e  = t + i * 256;
        int r  = e >> 7;
        int dq = e & 127;
        float4 v = *(const float4*)&Qg[r * DM + dq * 4];
        v.x *= scale; v.y *= scale; v.z *= scale; v.w *= scale;
        *(float4*)&sQ[r * DM + dq * 4] = v;
    }
    if (t < 32) { sM[t] = -INFINITY; sL[t] = 0.f; }

    // PV microtile assignment: 8 rows x 8 cols per thread
    const int pr0   = (w & 3) * 8;               // base q-row for PV
    const int pc0   = (w >> 2) * 256 + lane * 8; // base col  for PV
    const int r0    = w * 4;                     // QK rows

    float acc[8][8];
    #pragma unroll
    for (int r = 0; r < 8; r++)
        #pragma unroll
        for (int c = 0; c < 8; c++) acc[r][c] = 0.f;

    __syncthreads();

    for (int kt = 0; kt <= qt; kt++) {
        const int k0 = kt * 32;
        const float* Kg = g_k + ((size_t)b * SEQ + k0) * DM;
        const float* Vg = g_v + ((size_t)b * SEQ + k0) * DM;

        // Load K (transposed into sKt) and V
        #pragma unroll
        for (int i = 0; i < 16; i++) {
            int e  = t + i * 256;
            int r  = e >> 7;
            int dq = e & 127;
            int d  = dq * 4;
            float4 kv = *(const float4*)&Kg[r * DM + d];
            sKt[(d + 0) * 33 + r] = kv.x;
            sKt[(d + 1) * 33 + r] = kv.y;
            sKt[(d + 2) * 33 + r] = kv.z;
            sKt[(d + 3) * 33 + r] = kv.w;
            float4 vv = *(const float4*)&Vg[r * DM + d];
            *(float4*)&sV[r * DM + d] = vv;
        }
        __syncthreads();

        // ---- S = Q K^T (each lane: 4 rows x 1 col) ----
        float s0 = 0.f, s1 = 0.f, s2 = 0.f, s3 = 0.f;
        #pragma unroll 8
        for (int d = 0; d < DM; d += 4) {
            float ka = sKt[(d + 0) * 33 + lane];
            float kb = sKt[(d + 1) * 33 + lane];
            float kc = sKt[(d + 2) * 33 + lane];
            float kd = sKt[(d + 3) * 33 + lane];
            float4 qa = *(const float4*)&sQ[(r0 + 0) * DM + d];
            s0 += qa.x * ka + qa.y * kb + qa.z * kc + qa.w * kd;
            float4 qb = *(const float4*)&sQ[(r0 + 1) * DM + d];
            s1 += qb.x * ka + qb.y * kb + qb.z * kc + qb.w * kd;
            float4 qc = *(const float4*)&sQ[(r0 + 2) * DM + d];
            s2 += qc.x * ka + qc.y * kb + qc.z * kc + qc.w * kd;
            float4 qd = *(const float4*)&sQ[(r0 + 3) * DM + d];
            s3 += qd.x * ka + qd.y * kb + qd.z * kc + qd.w * kd;
        }

        // ---- online softmax per row (row values live across lanes) ----
        float sv[4] = { s0, s1, s2, s3 };
        const bool diag = (kt == qt);
        #pragma unroll
        for (int rr = 0; rr < 4; rr++) {
            float s = sv[rr];
            if (diag && (k0 + lane > q0 + r0 + rr)) s = -INFINITY;
            float mx = s;
            #pragma unroll
            for (int off = 16; off; off >>= 1)
                mx = fmaxf(mx, __shfl_xor_sync(0xffffffffu, mx, off));
            float mold = sM[r0 + rr];
            float mnew = fmaxf(mold, mx);
            float p = __expf(s - mnew);
            float psum = p;
            #pragma unroll
            for (int off = 16; off; off >>= 1)
                psum += __shfl_xor_sync(0xffffffffu, psum, off);
            float alpha = __expf(mold - mnew);
            if (lane == 0) {
                sM[r0 + rr]  = mnew;
                sL[r0 + rr]  = sL[r0 + rr] * alpha + psum;
                sAl[r0 + rr] = alpha;
            }
            sS[(r0 + rr) * 32 + lane] = p;
        }
        __syncthreads();

        // ---- O = alpha*O + P V  (8x8 register microtile) ----
        #pragma unroll
        for (int r = 0; r < 8; r++) {
            float al = sAl[pr0 + r];
            #pragma unroll
            for (int c = 0; c < 8; c++) acc[r][c] *= al;
        }
        #pragma unroll 4
        for (int j = 0; j < 32; j++) {
            float4 v0 = *(const float4*)&sV[j * DM + pc0];
            float4 v1 = *(const float4*)&sV[j * DM + pc0 + 4];
            #pragma unroll
            for (int r = 0; r < 8; r++) {
                float p = sS[(pr0 + r) * 32 + j];
                acc[r][0] += p * v0.x;
                acc[r][1] += p * v0.y;
                acc[r][2] += p * v0.z;
                acc[r][3] += p * v0.w;
                acc[r][4] += p * v1.x;
                acc[r][5] += p * v1.y;
                acc[r][6] += p * v1.z;
                acc[r][7] += p * v1.w;
            }
        }
        __syncthreads();
    }

    // Normalize and write context
    #pragma unroll
    for (int r = 0; r < 8; r++) {
        float linv = 1.0f / sL[pr0 + r];
        float* Og = g_ctx + ((size_t)b * SEQ + q0 + pr0 + r) * DM + pc0;
        float4 o0 = make_float4(acc[r][0] * linv, acc[r][1] * linv,
                                acc[r][2] * linv, acc[r][3] * linv);
        float4 o1 = make_float4(acc[r][4] * linv, acc[r][5] * linv,
                                acc[r][6] * linv, acc[r][7] * linv);
        *(float4*)&Og[0] = o0;
        *(float4*)&Og[4] = o1;
    }
}

// ---------------------------------------------------------------------------
extern "C" void kernel_launch(void* const* d_in, const int* in_sizes, int n_in,
                              void* d_out, int out_size) {
    (void)in_sizes; (void)n_in; (void)out_size;
    const float* x  = (const float*)d_in[0];
    const float* Wq = (const float*)d_in[1];
    const float* Wk = (const float*)d_in[2];
    const float* Wv = (const float*)d_in[3];
    const float* Wo = (const float*)d_in[4];
    float* out = (float*)d_out;

    qkv_proj<<<dim3(DM / BN, MROWS / BM, 3), 256>>>(x, Wq, Wk, Wv);

    cudaFuncSetAttribute(attn_kernel,
                         cudaFuncAttributeMaxDynamicSharedMemorySize,
                         ATTN_SMEM_BYTES);
    attn_kernel<<<dim3(SEQ / 32, BATCH), 256, ATTN_SMEM_BYTES>>>();

    out_proj<<<dim3(DM / BN, MROWS / BM), 256>>>(Wo, out);
}

// round 4
// speedup vs baseline: 4.3590x; 1.0015x over previous
#include <cuda_runtime.h>
#include <math.h>

#define BATCH 4
#define SEQ   4096
#define DM    512
#define MROWS (BATCH*SEQ)

// Scratch (device globals: allocation-free per harness rules). 4 x 32MB.
__device__ float g_q[MROWS*DM];
__device__ float g_k[MROWS*DM];
__device__ float g_v[MROWS*DM];
__device__ float g_ctx[MROWS*DM];

// ---------------------------------------------------------------------------
// GEMM: C[M,N] = A[M,512] @ W[N,512]^T   (both row-major, K contiguous)
// 64x64 tile, BK=32, 256 threads, 4x4 microtile, transposed smem tiles.
// ---------------------------------------------------------------------------
#define BM  64
#define BN  64
#define BKK 32

__device__ __forceinline__ void gemm_body(const float* __restrict__ A,
                                          const float* __restrict__ W,
                                          float* __restrict__ C) {
    __shared__ float sA[BKK][BM + 4];
    __shared__ float sB[BKK][BN + 4];
    const int m0 = blockIdx.y * BM;
    const int n0 = blockIdx.x * BN;
    const int t  = threadIdx.x;
    const int tx = t & 15;
    const int ty = t >> 4;

    float acc[4][4];
    #pragma unroll
    for (int i = 0; i < 4; i++)
        #pragma unroll
        for (int j = 0; j < 4; j++) acc[i][j] = 0.f;

    for (int k0 = 0; k0 < DM; k0 += BKK) {
        #pragma unroll
        for (int i = 0; i < 8; i++) {
            int e = t + i * 256;
            int k = e & 31;
            int m = e >> 5;
            sA[k][m] = A[(size_t)(m0 + m) * DM + k0 + k];
            sB[k][m] = W[(size_t)(n0 + m) * DM + k0 + k];
        }
        __syncthreads();

        #pragma unroll 8
        for (int kk = 0; kk < BKK; kk++) {
            float4 a = *(const float4*)&sA[kk][ty * 4];
            float4 b = *(const float4*)&sB[kk][tx * 4];
            acc[0][0] += a.x * b.x; acc[0][1] += a.x * b.y; acc[0][2] += a.x * b.z; acc[0][3] += a.x * b.w;
            acc[1][0] += a.y * b.x; acc[1][1] += a.y * b.y; acc[1][2] += a.y * b.z; acc[1][3] += a.y * b.w;
            acc[2][0] += a.z * b.x; acc[2][1] += a.z * b.y; acc[2][2] += a.z * b.z; acc[2][3] += a.z * b.w;
            acc[3][0] += a.w * b.x; acc[3][1] += a.w * b.y; acc[3][2] += a.w * b.z; acc[3][3] += a.w * b.w;
        }
        __syncthreads();
    }

    #pragma unroll
    for (int i = 0; i < 4; i++) {
        float4 o = make_float4(acc[i][0], acc[i][1], acc[i][2], acc[i][3]);
        *(float4*)&C[(size_t)(m0 + ty * 4 + i) * DM + n0 + tx * 4] = o;
    }
}

__global__ void __launch_bounds__(256, 1)
qkv_proj(const float* __restrict__ x,
         const float* __restrict__ Wq,
         const float* __restrict__ Wk,
         const float* __restrict__ Wv) {
    const float* W;
    float* C;
    if (blockIdx.z == 0)      { W = Wq; C = g_q; }
    else if (blockIdx.z == 1) { W = Wk; C = g_k; }
    else                      { W = Wv; C = g_v; }
    gemm_body(x, W, C);
}

__global__ void __launch_bounds__(256, 1)
out_proj(const float* __restrict__ Wo, float* __restrict__ out) {
    gemm_body(g_ctx, Wo, out);
}

// ---------------------------------------------------------------------------
// Causal flash attention, fp32. 32 queries x 32 keys per step, D=512.
// 256 threads.
//   QK^T : warp w owns rows 4w..4w+3, lane = key column (unchanged).
//   PV   : warp w owns q-rows (w&3)*8..+7, cols (w>>2)*256 + lane*8..+7.
//          8x8 register microtile -> V read ONCE per 8 q-rows, conflict-free
//          coalesced LDS.128 (lanes consecutive 32B).
// ---------------------------------------------------------------------------
#define SQ_F   (32 * 512)
#define SKT_F  (512 * 33)
#define SV_F   (32 * 512)
#define SS_F   (32 * 32)
#define ATTN_SMEM_FLOATS (SQ_F + SKT_F + SV_F + SS_F + 96)
#define ATTN_SMEM_BYTES  (ATTN_SMEM_FLOATS * 4)

__global__ void __launch_bounds__(256, 1) attn_kernel() {
    extern __shared__ float sh[];
    float* sQ  = sh;                 // [32][512], pre-scaled by 1/sqrt(D)
    float* sKt = sQ  + SQ_F;         // [512][33]  (K transposed, pad 33)
    float* sV  = sKt + SKT_F;        // [32][512]
    float* sS  = sV  + SV_F;         // [32][32]   probabilities
    float* sM  = sS  + SS_F;         // [32] running max
    float* sL  = sM  + 32;           // [32] running sum
    float* sAl = sL  + 32;           // [32] per-step rescale

    const int b    = blockIdx.y;
    const int qt   = gridDim.x - 1 - blockIdx.x;   // longest-first scheduling
    const int q0   = qt * 32;
    const int t    = threadIdx.x;
    const int lane = t & 31;
    const int w    = t >> 5;
    const float scale = 0.04419417382415922f;      // 1/sqrt(512)

    // Load + pre-scale Q tile
    const float* Qg = g_q + ((size_t)b * SEQ + q0) * DM;
    #pragma unroll
    for (int i = 0; i < 16; i++) {
        int e  = t + i * 256;
        int r  = e >> 7;
        int dq = e & 127;
        float4 v = *(const float4*)&Qg[r * DM + dq * 4];
        v.x *= scale; v.y *= scale; v.z *= scale; v.w *= scale;
        *(float4*)&sQ[r * DM + dq * 4] = v;
    }
    if (t < 32) { sM[t] = -INFINITY; sL[t] = 0.f; }

    // PV microtile assignment: 8 rows x 8 cols per thread
    const int pr0   = (w & 3) * 8;               // base q-row for PV
    const int pc0   = (w >> 2) * 256 + lane * 8; // base col  for PV
    const int r0    = w * 4;                     // QK rows

    float acc[8][8];
    #pragma unroll
    for (int r = 0; r < 8; r++)
        #pragma unroll
        for (int c = 0; c < 8; c++) acc[r][c] = 0.f;

    __syncthreads();

    for (int kt = 0; kt <= qt; kt++) {
        const int k0 = kt * 32;
        const float* Kg = g_k + ((size_t)b * SEQ + k0) * DM;
        const float* Vg = g_v + ((size_t)b * SEQ + k0) * DM;

        // Load K (transposed into sKt) and V
        #pragma unroll
        for (int i = 0; i < 16; i++) {
            int e  = t + i * 256;
            int r  = e >> 7;
            int dq = e & 127;
            int d  = dq * 4;
            float4 kv = *(const float4*)&Kg[r * DM + d];
            sKt[(d + 0) * 33 + r] = kv.x;
            sKt[(d + 1) * 33 + r] = kv.y;
            sKt[(d + 2) * 33 + r] = kv.z;
            sKt[(d + 3) * 33 + r] = kv.w;
            float4 vv = *(const float4*)&Vg[r * DM + d];
            *(float4*)&sV[r * DM + d] = vv;
        }
        __syncthreads();

        // ---- S = Q K^T (each lane: 4 rows x 1 col) ----
        float s0 = 0.f, s1 = 0.f, s2 = 0.f, s3 = 0.f;
        #pragma unroll 8
        for (int d = 0; d < DM; d += 4) {
            float ka = sKt[(d + 0) * 33 + lane];
            float kb = sKt[(d + 1) * 33 + lane];
            float kc = sKt[(d + 2) * 33 + lane];
            float kd = sKt[(d + 3) * 33 + lane];
            float4 qa = *(const float4*)&sQ[(r0 + 0) * DM + d];
            s0 += qa.x * ka + qa.y * kb + qa.z * kc + qa.w * kd;
            float4 qb = *(const float4*)&sQ[(r0 + 1) * DM + d];
            s1 += qb.x * ka + qb.y * kb + qb.z * kc + qb.w * kd;
            float4 qc = *(const float4*)&sQ[(r0 + 2) * DM + d];
            s2 += qc.x * ka + qc.y * kb + qc.z * kc + qc.w * kd;
            float4 qd = *(const float4*)&sQ[(r0 + 3) * DM + d];
            s3 += qd.x * ka + qd.y * kb + qd.z * kc + qd.w * kd;
        }

        // ---- online softmax per row (row values live across lanes) ----
        float sv[4] = { s0, s1, s2, s3 };
        const bool diag = (kt == qt);
        #pragma unroll
        for (int rr = 0; rr < 4; rr++) {
            float s = sv[rr];
            if (diag && (k0 + lane > q0 + r0 + rr)) s = -INFINITY;
            float mx = s;
            #pragma unroll
            for (int off = 16; off; off >>= 1)
                mx = fmaxf(mx, __shfl_xor_sync(0xffffffffu, mx, off));
            float mold = sM[r0 + rr];
            float mnew = fmaxf(mold, mx);
            float p = __expf(s - mnew);
            float psum = p;
            #pragma unroll
            for (int off = 16; off; off >>= 1)
                psum += __shfl_xor_sync(0xffffffffu, psum, off);
            float alpha = __expf(mold - mnew);
            if (lane == 0) {
                sM[r0 + rr]  = mnew;
                sL[r0 + rr]  = sL[r0 + rr] * alpha + psum;
                sAl[r0 + rr] = alpha;
            }
            sS[(r0 + rr) * 32 + lane] = p;
        }
        __syncthreads();

        // ---- O = alpha*O + P V  (8x8 register microtile) ----
        #pragma unroll
        for (int r = 0; r < 8; r++) {
            float al = sAl[pr0 + r];
            #pragma unroll
            for (int c = 0; c < 8; c++) acc[r][c] *= al;
        }
        #pragma unroll 4
        for (int j = 0; j < 32; j++) {
            float4 v0 = *(const float4*)&sV[j * DM + pc0];
            float4 v1 = *(const float4*)&sV[j * DM + pc0 + 4];
            #pragma unroll
            for (int r = 0; r < 8; r++) {
                float p = sS[(pr0 + r) * 32 + j];
                acc[r][0] += p * v0.x;
                acc[r][1] += p * v0.y;
                acc[r][2] += p * v0.z;
                acc[r][3] += p * v0.w;
                acc[r][4] += p * v1.x;
                acc[r][5] += p * v1.y;
                acc[r][6] += p * v1.z;
                acc[r][7] += p * v1.w;
            }
        }
        __syncthreads();
    }

    // Normalize and write context
    #pragma unroll
    for (int r = 0; r < 8; r++) {
        float linv = 1.0f / sL[pr0 + r];
        float* Og = g_ctx + ((size_t)b * SEQ + q0 + pr0 + r) * DM + pc0;
        float4 o0 = make_float4(acc[r][0] * linv, acc[r][1] * linv,
                                acc[r][2] * linv, acc[r][3] * linv);
        float4 o1 = make_float4(acc[r][4] * linv, acc[r][5] * linv,
                                acc[r][6] * linv, acc[r][7] * linv);
        *(float4*)&Og[0] = o0;
        *(float4*)&Og[4] = o1;
    }
}

// ---------------------------------------------------------------------------
extern "C" void kernel_launch(void* const* d_in, const int* in_sizes, int n_in,
                              void* d_out, int out_size) {
    (void)in_sizes; (void)n_in; (void)out_size;
    const float* x  = (const float*)d_in[0];
    const float* Wq = (const float*)d_in[1];
    const float* Wk = (const float*)d_in[2];
    const float* Wv = (const float*)d_in[3];
    const float* Wo = (const float*)d_in[4];
    float* out = (float*)d_out;

    qkv_proj<<<dim3(DM / BN, MROWS / BM, 3), 256>>>(x, Wq, Wk, Wv);

    cudaFuncSetAttribute(attn_kernel,
                         cudaFuncAttributeMaxDynamicSharedMemorySize,
                         ATTN_SMEM_BYTES);
    attn_kernel<<<dim3(SEQ / 32, BATCH), 256, ATTN_SMEM_BYTES>>>();

    out_proj<<<dim3(DM / BN, MROWS / BM), 256>>>(Wo, out);
}

// round 9
// speedup vs baseline: 5.1730x; 1.1867x over previous
#include <cuda_runtime.h>
#include <math.h>
#include <stdint.h>

#define BATCH 4
#define SEQ   4096
#define DM    512
#define MROWS (BATCH*SEQ)

__device__ float g_q[MROWS*DM];
__device__ float g_k[MROWS*DM];
__device__ float g_v[MROWS*DM];
__device__ float g_ctx[MROWS*DM];

// tf32 round-to-nearest via integer ops (no cvt.rna.tf32 — isolates the mma path)
__device__ __forceinline__ float t32f(float x) {
    uint32_t u = __float_as_uint(x);
    u = (u + 0x1000u + ((u >> 13) & 1u)) & 0xFFFFE000u;
    return __uint_as_float(u);
}
__device__ __forceinline__ uint32_t fu(float x) { return __float_as_uint(x); }

// D += A(16x8) @ B(8x8), tf32 operands, fp32 accumulate
__device__ __forceinline__ void mm8(float* c, const uint32_t* a, uint32_t b0, uint32_t b1) {
    asm volatile("mma.sync.aligned.m16n8k8.row.col.f32.tf32.tf32.f32 "
        "{%0,%1,%2,%3},{%4,%5,%6,%7},{%8,%9},{%0,%1,%2,%3};"
        : "+f"(c[0]), "+f"(c[1]), "+f"(c[2]), "+f"(c[3])
        : "r"(a[0]), "r"(a[1]), "r"(a[2]), "r"(a[3]), "r"(b0), "r"(b1));
}

// ================= tf32 MMA projection GEMM: C[16384,512] = A @ W^T =================
// 256 thr (8 warps), tile 128M x 64N, K-chunk 32, direct conflict-free LDS fragments.
#define PLDA 36

__device__ __forceinline__ void proj_body(const float* __restrict__ A,
                                          const float* __restrict__ W,
                                          float* __restrict__ C) {
    __shared__ float sA[128 * PLDA];
    __shared__ float sW[64 * PLDA];
    const int t = threadIdx.x, w = t >> 5, lane = t & 31;
    const int g = lane >> 2, q4 = lane & 3;
    const int m0 = blockIdx.y * 128, n0 = blockIdx.x * 64;
    const int wm = (w & 3) * 32, wn = (w >> 2) * 32;

    float acc[2][4][4];
    #pragma unroll
    for (int a = 0; a < 2; a++)
        #pragma unroll
        for (int b = 0; b < 4; b++)
            #pragma unroll
            for (int c = 0; c < 4; c++) acc[a][b][c] = 0.f;

    for (int k0 = 0; k0 < DM; k0 += 32) {
        #pragma unroll
        for (int i = 0; i < 4; i++) {          // A: 128x32
            int e = t + i * 256, r = e >> 3, j = e & 7;
            float4 v = *(const float4*)&A[(size_t)(m0 + r) * DM + k0 + j * 4];
            float* d = &sA[r * PLDA + j * 4];
            d[0] = t32f(v.x); d[1] = t32f(v.y); d[2] = t32f(v.z); d[3] = t32f(v.w);
        }
        #pragma unroll
        for (int i = 0; i < 2; i++) {          // W: 64x32
            int e = t + i * 256, r = e >> 3, j = e & 7;
            float4 v = *(const float4*)&W[(size_t)(n0 + r) * DM + k0 + j * 4];
            float* d = &sW[r * PLDA + j * 4];
            d[0] = t32f(v.x); d[1] = t32f(v.y); d[2] = t32f(v.z); d[3] = t32f(v.w);
        }
        __syncthreads();
        #pragma unroll
        for (int kk = 0; kk < 32; kk += 8) {
            uint32_t af[2][4];
            #pragma unroll
            for (int mt = 0; mt < 2; mt++) {
                int base = (wm + mt * 16 + g) * PLDA + kk + q4;
                af[mt][0] = fu(sA[base]);
                af[mt][1] = fu(sA[base + 8 * PLDA]);
                af[mt][2] = fu(sA[base + 4]);
                af[mt][3] = fu(sA[base + 8 * PLDA + 4]);
            }
            #pragma unroll
            for (int nt = 0; nt < 4; nt++) {
                int bb = (wn + nt * 8 + g) * PLDA + kk + q4;
                uint32_t b0 = fu(sW[bb]), b1 = fu(sW[bb + 4]);
                mm8(acc[0][nt], af[0], b0, b1);
                mm8(acc[1][nt], af[1], b0, b1);
            }
        }
        __syncthreads();
    }
    #pragma unroll
    for (int mt = 0; mt < 2; mt++)
        #pragma unroll
        for (int nt = 0; nt < 4; nt++) {
            int r0 = m0 + wm + mt * 16 + g;
            int col = n0 + wn + nt * 8 + 2 * q4;
            float* a = acc[mt][nt];
            C[(size_t)r0 * DM + col]           = a[0];
            C[(size_t)r0 * DM + col + 1]       = a[1];
            C[(size_t)(r0 + 8) * DM + col]     = a[2];
            C[(size_t)(r0 + 8) * DM + col + 1] = a[3];
        }
}

__global__ void __launch_bounds__(256, 1)
qkv_proj(const float* __restrict__ x, const float* __restrict__ Wq,
         const float* __restrict__ Wk, const float* __restrict__ Wv) {
    if (blockIdx.z == 0)      proj_body(x, Wq, g_q);
    else if (blockIdx.z == 1) proj_body(x, Wk, g_k);
    else                      proj_body(x, Wv, g_v);
}

__global__ void __launch_bounds__(256, 1)
out_proj(const float* __restrict__ Wo, float* __restrict__ out) {
    proj_body(g_ctx, Wo, out);
}

// ============ PROVEN round-2 SIMT flash attention (fp32), verbatim ============
#define SQ_F   (32 * 512)
#define SKT_F  (512 * 33)
#define SV_F   (32 * 512)
#define SS_F   (32 * 32)
#define ATTN_SMEM_FLOATS (SQ_F + SKT_F + SV_F + SS_F + 96)
#define ATTN_SMEM_BYTES  (ATTN_SMEM_FLOATS * 4)

__global__ void __launch_bounds__(256, 1) attn_kernel() {
    extern __shared__ float sh[];
    float* sQ  = sh;
    float* sKt = sQ  + SQ_F;
    float* sV  = sKt + SKT_F;
    float* sS  = sV  + SV_F;
    float* sM  = sS  + SS_F;
    float* sL  = sM  + 32;
    float* sAl = sL  + 32;

    const int b    = blockIdx.y;
    const int qt   = gridDim.x - 1 - blockIdx.x;
    const int q0   = qt * 32;
    const int t    = threadIdx.x;
    const int lane = t & 31;
    const int w    = t >> 5;
    const float scale = 0.04419417382415922f;

    const float* Qg = g_q + ((size_t)b * SEQ + q0) * DM;
    #pragma unroll
    for (int i = 0; i < 16; i++) {
        int e  = t + i * 256;
        int r  = e >> 7;
        int dq = e & 127;
        float4 v = *(const float4*)&Qg[r * DM + dq * 4];
        v.x *= scale; v.y *= scale; v.z *= scale; v.w *= scale;
        *(float4*)&sQ[r * DM + dq * 4] = v;
    }
    if (t < 32) { sM[t] = -INFINITY; sL[t] = 0.f; }

    const int pr0 = (w & 3) * 8;
    const int pc0 = (w >> 2) * 256 + lane * 8;
    const int r0  = w * 4;

    float acc[8][8];
    #pragma unroll
    for (int r = 0; r < 8; r++)
        #pragma unroll
        for (int c = 0; c < 8; c++) acc[r][c] = 0.f;

    __syncthreads();

    for (int kt = 0; kt <= qt; kt++) {
        const int k0 = kt * 32;
        const float* Kg = g_k + ((size_t)b * SEQ + k0) * DM;
        const float* Vg = g_v + ((size_t)b * SEQ + k0) * DM;

        #pragma unroll
        for (int i = 0; i < 16; i++) {
            int e  = t + i * 256;
            int r  = e >> 7;
            int dq = e & 127;
            int d  = dq * 4;
            float4 kv = *(const float4*)&Kg[r * DM + d];
            sKt[(d + 0) * 33 + r] = kv.x;
            sKt[(d + 1) * 33 + r] = kv.y;
            sKt[(d + 2) * 33 + r] = kv.z;
            sKt[(d + 3) * 33 + r] = kv.w;
            float4 vv = *(const float4*)&Vg[r * DM + d];
            *(float4*)&sV[r * DM + d] = vv;
        }
        __syncthreads();

        float s0 = 0.f, s1 = 0.f, s2 = 0.f, s3 = 0.f;
        #pragma unroll 8
        for (int d = 0; d < DM; d += 4) {
            float ka = sKt[(d + 0) * 33 + lane];
            float kb = sKt[(d + 1) * 33 + lane];
            float kc = sKt[(d + 2) * 33 + lane];
            float kd = sKt[(d + 3) * 33 + lane];
            float4 qa = *(const float4*)&sQ[(r0 + 0) * DM + d];
            s0 += qa.x * ka + qa.y * kb + qa.z * kc + qa.w * kd;
            float4 qb = *(const float4*)&sQ[(r0 + 1) * DM + d];
            s1 += qb.x * ka + qb.y * kb + qb.z * kc + qb.w * kd;
            float4 qc = *(const float4*)&sQ[(r0 + 2) * DM + d];
            s2 += qc.x * ka + qc.y * kb + qc.z * kc + qc.w * kd;
            float4 qd = *(const float4*)&sQ[(r0 + 3) * DM + d];
            s3 += qd.x * ka + qd.y * kb + qd.z * kc + qd.w * kd;
        }

        float sv[4] = { s0, s1, s2, s3 };
        const bool diag = (kt == qt);
        #pragma unroll
        for (int rr = 0; rr < 4; rr++) {
            float s = sv[rr];
            if (diag && (k0 + lane > q0 + r0 + rr)) s = -INFINITY;
            float mx = s;
            #pragma unroll
            for (int off = 16; off; off >>= 1)
                mx = fmaxf(mx, __shfl_xor_sync(0xffffffffu, mx, off));
            float mold = sM[r0 + rr];
            float mnew = fmaxf(mold, mx);
            float p = __expf(s - mnew);
            float psum = p;
            #pragma unroll
            for (int off = 16; off; off >>= 1)
                psum += __shfl_xor_sync(0xffffffffu, psum, off);
            float alpha = __expf(mold - mnew);
            if (lane == 0) {
                sM[r0 + rr]  = mnew;
                sL[r0 + rr]  = sL[r0 + rr] * alpha + psum;
                sAl[r0 + rr] = alpha;
            }
            sS[(r0 + rr) * 32 + lane] = p;
        }
        __syncthreads();

        #pragma unroll
        for (int r = 0; r < 8; r++) {
            float al = sAl[pr0 + r];
            #pragma unroll
            for (int c = 0; c < 8; c++) acc[r][c] *= al;
        }
        #pragma unroll 4
        for (int j = 0; j < 32; j++) {
            float4 v0 = *(const float4*)&sV[j * DM + pc0];
            float4 v1 = *(const float4*)&sV[j * DM + pc0 + 4];
            #pragma unroll
            for (int r = 0; r < 8; r++) {
                float p = sS[(pr0 + r) * 32 + j];
                acc[r][0] += p * v0.x;
                acc[r][1] += p * v0.y;
                acc[r][2] += p * v0.z;
                acc[r][3] += p * v0.w;
                acc[r][4] += p * v1.x;
                acc[r][5] += p * v1.y;
                acc[r][6] += p * v1.z;
                acc[r][7] += p * v1.w;
            }
        }
        __syncthreads();
    }

    #pragma unroll
    for (int r = 0; r < 8; r++) {
        float linv = 1.0f / sL[pr0 + r];
        float* Og = g_ctx + ((size_t)b * SEQ + q0 + pr0 + r) * DM + pc0;
        float4 o0 = make_float4(acc[r][0] * linv, acc[r][1] * linv,
                                acc[r][2] * linv, acc[r][3] * linv);
        float4 o1 = make_float4(acc[r][4] * linv, acc[r][5] * linv,
                                acc[r][6] * linv, acc[r][7] * linv);
        *(float4*)&Og[0] = o0;
        *(float4*)&Og[4] = o1;
    }
}

// ---------------------------------------------------------------------------
extern "C" void kernel_launch(void* const* d_in, const int* in_sizes, int n_in,
                              void* d_out, int out_size) {
    (void)in_sizes; (void)n_in; (void)out_size;
    const float* x  = (const float*)d_in[0];
    const float* Wq = (const float*)d_in[1];
    const float* Wk = (const float*)d_in[2];
    const float* Wv = (const float*)d_in[3];
    const float* Wo = (const float*)d_in[4];
    float* out = (float*)d_out;

    qkv_proj<<<dim3(8, 128, 3), 256>>>(x, Wq, Wk, Wv);

    cudaFuncSetAttribute(attn_kernel,
                         cudaFuncAttributeMaxDynamicSharedMemorySize,
                         ATTN_SMEM_BYTES);
    attn_kernel<<<dim3(SEQ / 32, BATCH), 256, ATTN_SMEM_BYTES>>>();

    out_proj<<<dim3(8, 128), 256>>>(Wo, out);
}

// round 10
// speedup vs baseline: 7.9877x; 1.5441x over previous
#include <cuda_runtime.h>
#include <math.h>
#include <stdint.h>

#define BATCH 4
#define SEQ   4096
#define DM    512
#define MROWS (BATCH*SEQ)

__device__ float g_q[MROWS*DM];
__device__ float g_k[MROWS*DM];
__device__ float g_v[MROWS*DM];
__device__ float g_ctx[MROWS*DM];

// tf32 round-to-nearest via integer ops (cvt.rna.tf32 is broken on this target!)
__device__ __forceinline__ float t32f(float x) {
    uint32_t u = __float_as_uint(x);
    u = (u + 0x1000u + ((u >> 13) & 1u)) & 0xFFFFE000u;
    return __uint_as_float(u);
}
__device__ __forceinline__ uint32_t fu(float x) { return __float_as_uint(x); }
// split fp32 -> tf32 hi + tf32 lo (lo error ~2^-24, negligible)
__device__ __forceinline__ void spl(float x, uint32_t& h, uint32_t& l) {
    float hf = t32f(x);
    h = fu(hf);
    l = fu(x - hf);
}

// D += A(16x8) @ B(8x8), tf32 operands, fp32 accumulate (validated on HW in R9)
__device__ __forceinline__ void mm8(float* c, const uint32_t* a, uint32_t b0, uint32_t b1) {
    asm volatile("mma.sync.aligned.m16n8k8.row.col.f32.tf32.tf32.f32 "
        "{%0,%1,%2,%3},{%4,%5,%6,%7},{%8,%9},{%0,%1,%2,%3};"
        : "+f"(c[0]), "+f"(c[1]), "+f"(c[2]), "+f"(c[3])
        : "r"(a[0]), "r"(a[1]), "r"(a[2]), "r"(a[3]), "r"(b0), "r"(b1));
}

// ============== tf32 MMA projection GEMM (VERIFIED round 9, unchanged) ==============
#define PLDA 36

__device__ __forceinline__ void proj_body(const float* __restrict__ A,
                                          const float* __restrict__ W,
                                          float* __restrict__ C) {
    __shared__ float sA[128 * PLDA];
    __shared__ float sW[64 * PLDA];
    const int t = threadIdx.x, w = t >> 5, lane = t & 31;
    const int g = lane >> 2, q4 = lane & 3;
    const int m0 = blockIdx.y * 128, n0 = blockIdx.x * 64;
    const int wm = (w & 3) * 32, wn = (w >> 2) * 32;

    float acc[2][4][4];
    #pragma unroll
    for (int a = 0; a < 2; a++)
        #pragma unroll
        for (int b = 0; b < 4; b++)
            #pragma unroll
            for (int c = 0; c < 4; c++) acc[a][b][c] = 0.f;

    for (int k0 = 0; k0 < DM; k0 += 32) {
        #pragma unroll
        for (int i = 0; i < 4; i++) {
            int e = t + i * 256, r = e >> 3, j = e & 7;
            float4 v = *(const float4*)&A[(size_t)(m0 + r) * DM + k0 + j * 4];
            float* d = &sA[r * PLDA + j * 4];
            d[0] = t32f(v.x); d[1] = t32f(v.y); d[2] = t32f(v.z); d[3] = t32f(v.w);
        }
        #pragma unroll
        for (int i = 0; i < 2; i++) {
            int e = t + i * 256, r = e >> 3, j = e & 7;
            float4 v = *(const float4*)&W[(size_t)(n0 + r) * DM + k0 + j * 4];
            float* d = &sW[r * PLDA + j * 4];
            d[0] = t32f(v.x); d[1] = t32f(v.y); d[2] = t32f(v.z); d[3] = t32f(v.w);
        }
        __syncthreads();
        #pragma unroll
        for (int kk = 0; kk < 32; kk += 8) {
            uint32_t af[2][4];
            #pragma unroll
            for (int mt = 0; mt < 2; mt++) {
                int base = (wm + mt * 16 + g) * PLDA + kk + q4;
                af[mt][0] = fu(sA[base]);
                af[mt][1] = fu(sA[base + 8 * PLDA]);
                af[mt][2] = fu(sA[base + 4]);
                af[mt][3] = fu(sA[base + 8 * PLDA + 4]);
            }
            #pragma unroll
            for (int nt = 0; nt < 4; nt++) {
                int bb = (wn + nt * 8 + g) * PLDA + kk + q4;
                uint32_t b0 = fu(sW[bb]), b1 = fu(sW[bb + 4]);
                mm8(acc[0][nt], af[0], b0, b1);
                mm8(acc[1][nt], af[1], b0, b1);
            }
        }
        __syncthreads();
    }
    #pragma unroll
    for (int mt = 0; mt < 2; mt++)
        #pragma unroll
        for (int nt = 0; nt < 4; nt++) {
            int r0 = m0 + wm + mt * 16 + g;
            int col = n0 + wn + nt * 8 + 2 * q4;
            float* a = acc[mt][nt];
            C[(size_t)r0 * DM + col]           = a[0];
            C[(size_t)r0 * DM + col + 1]       = a[1];
            C[(size_t)(r0 + 8) * DM + col]     = a[2];
            C[(size_t)(r0 + 8) * DM + col + 1] = a[3];
        }
}

__global__ void __launch_bounds__(256, 1)
qkv_proj(const float* __restrict__ x, const float* __restrict__ Wq,
         const float* __restrict__ Wk, const float* __restrict__ Wv) {
    if (blockIdx.z == 0)      proj_body(x, Wq, g_q);
    else if (blockIdx.z == 1) proj_body(x, Wk, g_k);
    else                      proj_body(x, Wv, g_v);
}

__global__ void __launch_bounds__(256, 1)
out_proj(const float* __restrict__ Wo, float* __restrict__ out) {
    proj_body(g_ctx, Wo, out);
}

// ========= split-tf32 MMA flash attention: q-tile 32, k-tile 128, 256 thr =========
// smem fp32; hi/lo split happens in registers after each fragment load.
#define LDQ 516
#define LDK 132
#define OQ  0
#define OK2 16512
#define OS2 33408
#define OA2 37632
#define OL2 37664
#define A_WORDS 37696
#define A_BYTES (A_WORDS*4)

__global__ void __launch_bounds__(256, 1) attn() {
    extern __shared__ float sh[];
    float* sQ = sh + OQ;      // [32][516] fp32, pre-scaled
    float* sK = sh + OK2;     // [128][132] K or V chunk, fp32
    float* sS = sh + OS2;     // [32][132] scores -> probs
    float* sAlp = sh + OA2;
    float* sL = sh + OL2;
    const int t = threadIdx.x, w = t >> 5, lane = t & 31;
    const int g = lane >> 2, q4 = lane & 3;
    const int qt = 127 - blockIdx.x, b = blockIdx.y;  // longest-first
    const int q0 = qt * 32;
    const int mq = (w & 1) * 16;     // warp's 16 q-rows
    const int wn = (w >> 1) * 32;    // warp's 32-col group
    const int row = t >> 3, sub = t & 7;
    const int ktmax = (q0 + 31) >> 7;
    const float scale = 0.04419417382415922f;  // 1/sqrt(512)

    // stage full Q tile once (fp32, scaled)
    #pragma unroll
    for (int i = 0; i < 16; i++) {
        int e = t + i * 256, r = e >> 7, j = e & 127;
        float4 v = *(const float4*)&g_q[((size_t)b * SEQ + q0 + r) * DM + j * 4];
        v.x *= scale; v.y *= scale; v.z *= scale; v.w *= scale;
        *(float4*)&sQ[r * LDQ + j * 4] = v;
    }
    float oacc[4][4][4];   // [d-chunk][nt][frag]
    #pragma unroll
    for (int c = 0; c < 4; c++)
        #pragma unroll
        for (int nt = 0; nt < 4; nt++)
            #pragma unroll
            for (int i = 0; i < 4; i++) oacc[c][nt][i] = 0.f;
    float m_run = -INFINITY, l_run = 0.f;
    __syncthreads();

    for (int kt = 0; kt <= ktmax; kt++) {
        const int k0 = kt * 128;
        float sacc[4][4];
        #pragma unroll
        for (int nt = 0; nt < 4; nt++)
            #pragma unroll
            for (int i = 0; i < 4; i++) sacc[nt][i] = 0.f;

        // ---- S = Q K^T over 4 d-chunks (3-pass split-tf32) ----
        for (int c = 0; c < 4; c++) {
            #pragma unroll
            for (int i = 0; i < 16; i++) {       // K chunk 128x128 fp32
                int e = t + i * 256, r = e >> 5, j = e & 31;
                *(float4*)&sK[r * LDK + j * 4] =
                    *(const float4*)&g_k[((size_t)b * SEQ + k0 + r) * DM + c * 128 + j * 4];
            }
            __syncthreads();
            #pragma unroll
            for (int kk = 0; kk < 128; kk += 8) {
                int base = (mq + g) * LDQ + c * 128 + kk + q4;
                uint32_t ah[4], al[4];
                spl(sQ[base],               ah[0], al[0]);
                spl(sQ[base + 8 * LDQ],     ah[1], al[1]);
                spl(sQ[base + 4],           ah[2], al[2]);
                spl(sQ[base + 8 * LDQ + 4], ah[3], al[3]);
                #pragma unroll
                for (int nt = 0; nt < 4; nt++) {
                    int bb = (wn + nt * 8 + g) * LDK + kk + q4;
                    uint32_t b0h, b0l, b1h, b1l;
                    spl(sK[bb],     b0h, b0l);
                    spl(sK[bb + 4], b1h, b1l);
                    mm8(sacc[nt], ah, b0h, b1h);
                    mm8(sacc[nt], ah, b0l, b1l);
                    mm8(sacc[nt], al, b0h, b1h);
                }
            }
            __syncthreads();
        }
        // ---- S -> smem ----
        #pragma unroll
        for (int nt = 0; nt < 4; nt++) {
            int r0 = mq + g, col = wn + nt * 8 + 2 * q4;
            sS[r0 * LDK + col]           = sacc[nt][0];
            sS[r0 * LDK + col + 1]       = sacc[nt][1];
            sS[(r0 + 8) * LDK + col]     = sacc[nt][2];
            sS[(r0 + 8) * LDK + col + 1] = sacc[nt][3];
        }
        __syncthreads();
        // ---- online softmax: 8 threads/row, 16 keys each ----
        float sv[16], mx = -INFINITY;
        const bool lastt = (kt == ktmax);
        #pragma unroll
        for (int i = 0; i < 16; i++) {
            float s = sS[row * LDK + sub * 16 + i];
            if (lastt && (k0 + sub * 16 + i > q0 + row)) s = -INFINITY;
            sv[i] = s;
            mx = fmaxf(mx, s);
        }
        #pragma unroll
        for (int o = 1; o < 8; o <<= 1) mx = fmaxf(mx, __shfl_xor_sync(~0u, mx, o));
        float mnew = fmaxf(m_run, mx);
        float alpha = __expf(m_run - mnew);
        float ps = 0.f;
        #pragma unroll
        for (int i = 0; i < 16; i++) { sv[i] = __expf(sv[i] - mnew); ps += sv[i]; }
        #pragma unroll
        for (int o = 1; o < 8; o <<= 1) ps += __shfl_xor_sync(~0u, ps, o);
        l_run = l_run * alpha + ps;
        m_run = mnew;
        if (sub == 0) sAlp[row] = alpha;
        #pragma unroll
        for (int i = 0; i < 16; i++) sS[row * LDK + sub * 16 + i] = sv[i];
        __syncthreads();
        // ---- rescale O ----
        {
            float a0 = sAlp[mq + g], a1 = sAlp[mq + g + 8];
            #pragma unroll
            for (int c = 0; c < 4; c++)
                #pragma unroll
                for (int nt = 0; nt < 4; nt++) {
                    oacc[c][nt][0] *= a0; oacc[c][nt][1] *= a0;
                    oacc[c][nt][2] *= a1; oacc[c][nt][3] *= a1;
                }
        }
        // ---- O += P V over 4 d-chunks (V reuses sK; 3-pass split-tf32) ----
        for (int c = 0; c < 4; c++) {
            #pragma unroll
            for (int i = 0; i < 16; i++) {
                int e = t + i * 256, r = e >> 5, j = e & 31;
                *(float4*)&sK[r * LDK + j * 4] =
                    *(const float4*)&g_v[((size_t)b * SEQ + k0 + r) * DM + c * 128 + j * 4];
            }
            __syncthreads();
            #pragma unroll
            for (int kk = 0; kk < 128; kk += 8) {
                int base = (mq + g) * LDK + kk + q4;
                uint32_t ph[4], pl[4];
                spl(sS[base],               ph[0], pl[0]);
                spl(sS[base + 8 * LDK],     ph[1], pl[1]);
                spl(sS[base + 4],           ph[2], pl[2]);
                spl(sS[base + 8 * LDK + 4], ph[3], pl[3]);
                #pragma unroll
                for (int nt = 0; nt < 4; nt++) {
                    int bb = (kk + q4) * LDK + wn + nt * 8 + g;   // V[k][d]
                    uint32_t v0h, v0l, v1h, v1l;
                    spl(sK[bb],           v0h, v0l);
                    spl(sK[bb + 4 * LDK], v1h, v1l);
                    mm8(oacc[c][nt], ph, v0h, v1h);
                    mm8(oacc[c][nt], ph, v0l, v1l);
                    mm8(oacc[c][nt], pl, v0h, v1h);
                }
            }
            __syncthreads();
        }
    }
    // ---- epilogue ----
    if (sub == 0) sL[row] = l_run;
    __syncthreads();
    {
        float li0 = 1.f / sL[mq + g], li1 = 1.f / sL[mq + g + 8];
        #pragma unroll
        for (int c = 0; c < 4; c++)
            #pragma unroll
            for (int nt = 0; nt < 4; nt++) {
                int col = c * 128 + wn + nt * 8 + 2 * q4;
                size_t r0 = ((size_t)b * SEQ + q0 + mq + g) * DM;
                float* a = oacc[c][nt];
                g_ctx[r0 + col]              = a[0] * li0;
                g_ctx[r0 + col + 1]          = a[1] * li0;
                g_ctx[r0 + 8 * DM + col]     = a[2] * li1;
                g_ctx[r0 + 8 * DM + col + 1] = a[3] * li1;
            }
    }
}

extern "C" void kernel_launch(void* const* d_in, const int* in_sizes, int n_in,
                              void* d_out, int out_size) {
    (void)in_sizes; (void)n_in; (void)out_size;
    const float* x  = (const float*)d_in[0];
    const float* Wq = (const float*)d_in[1];
    const float* Wk = (const float*)d_in[2];
    const float* Wv = (const float*)d_in[3];
    const float* Wo = (const float*)d_in[4];
    float* out = (float*)d_out;

    qkv_proj<<<dim3(8, 128, 3), 256>>>(x, Wq, Wk, Wv);

    cudaFuncSetAttribute(attn, cudaFuncAttributeMaxDynamicSharedMemorySize, A_BYTES);
    attn<<<dim3(128, BATCH), 256, A_BYTES>>>();

    out_proj<<<dim3(8, 128), 256>>>(Wo, out);
}

// round 11
// speedup vs baseline: 11.9740x; 1.4990x over previous
#include <cuda_runtime.h>
#include <math.h>
#include <stdint.h>

#define BATCH 4
#define SEQ   4096
#define DM    512
#define MROWS (BATCH*SEQ)

__device__ float g_q[MROWS*DM];
__device__ float g_k[MROWS*DM];
__device__ float g_v[MROWS*DM];
__device__ float g_ctx[MROWS*DM];
// packed bf16 hi/lo operands for attention
__device__ __align__(16) uint16_t g_qh[MROWS*DM], g_ql[MROWS*DM];
__device__ __align__(16) uint16_t g_kh[MROWS*DM], g_kl[MROWS*DM];
__device__ __align__(16) uint16_t g_vth[MROWS*DM], g_vtl[MROWS*DM];  // [b][d][s]

__device__ __forceinline__ uint32_t fu(float x) { return __float_as_uint(x); }
// tf32 round (integer ops only — cvt.rna.tf32 is broken on this target)
__device__ __forceinline__ float t32f(float x) {
    uint32_t u = fu(x);
    u = (u + 0x1000u + ((u >> 13) & 1u)) & 0xFFFFE000u;
    return __uint_as_float(u);
}
// bf16 round-to-nearest-even, integer ops; returns fp32 bits of rounded value
__device__ __forceinline__ uint32_t bfr(float x) {
    uint32_t u = fu(x);
    return (u + 0x7FFFu + ((u >> 16) & 1u)) & 0xFFFF0000u;
}
// split (a,b) -> packed bf16 hi pair, packed bf16 lo pair
__device__ __forceinline__ void sp2b(float a, float b, uint32_t& h, uint32_t& l) {
    uint32_t ra = bfr(a), rb = bfr(b);
    h = (ra >> 16) | (rb & 0xFFFF0000u);
    float la = a - __uint_as_float(ra), lb = b - __uint_as_float(rb);
    uint32_t rla = bfr(la), rlb = bfr(lb);
    l = (rla >> 16) | (rlb & 0xFFFF0000u);
}

// tf32 m16n8k8 (VERIFIED R9) — used by projections
__device__ __forceinline__ void mm8(float* c, const uint32_t* a, uint32_t b0, uint32_t b1) {
    asm volatile("mma.sync.aligned.m16n8k8.row.col.f32.tf32.tf32.f32 "
        "{%0,%1,%2,%3},{%4,%5,%6,%7},{%8,%9},{%0,%1,%2,%3};"
        : "+f"(c[0]), "+f"(c[1]), "+f"(c[2]), "+f"(c[3])
        : "r"(a[0]), "r"(a[1]), "r"(a[2]), "r"(a[3]), "r"(b0), "r"(b1));
}
// bf16 m16n8k16 — attention
__device__ __forceinline__ void mm16(float* c, const uint32_t* a, uint32_t b0, uint32_t b1) {
    asm volatile("mma.sync.aligned.m16n8k16.row.col.f32.bf16.bf16.f32 "
        "{%0,%1,%2,%3},{%4,%5,%6,%7},{%8,%9},{%0,%1,%2,%3};"
        : "+f"(c[0]), "+f"(c[1]), "+f"(c[2]), "+f"(c[3])
        : "r"(a[0]), "r"(a[1]), "r"(a[2]), "r"(a[3]), "r"(b0), "r"(b1));
}

// ============== tf32 MMA projection GEMM (VERIFIED R9/R10, unchanged) ==============
#define PLDA 36

__device__ __forceinline__ void proj_body(const float* __restrict__ A,
                                          const float* __restrict__ W,
                                          float* __restrict__ C) {
    __shared__ float sA[128 * PLDA];
    __shared__ float sW[64 * PLDA];
    const int t = threadIdx.x, w = t >> 5, lane = t & 31;
    const int g = lane >> 2, q4 = lane & 3;
    const int m0 = blockIdx.y * 128, n0 = blockIdx.x * 64;
    const int wm = (w & 3) * 32, wn = (w >> 2) * 32;

    float acc[2][4][4];
    #pragma unroll
    for (int a = 0; a < 2; a++)
        #pragma unroll
        for (int b = 0; b < 4; b++)
            #pragma unroll
            for (int c = 0; c < 4; c++) acc[a][b][c] = 0.f;

    for (int k0 = 0; k0 < DM; k0 += 32) {
        #pragma unroll
        for (int i = 0; i < 4; i++) {
            int e = t + i * 256, r = e >> 3, j = e & 7;
            float4 v = *(const float4*)&A[(size_t)(m0 + r) * DM + k0 + j * 4];
            float* d = &sA[r * PLDA + j * 4];
            d[0] = t32f(v.x); d[1] = t32f(v.y); d[2] = t32f(v.z); d[3] = t32f(v.w);
        }
        #pragma unroll
        for (int i = 0; i < 2; i++) {
            int e = t + i * 256, r = e >> 3, j = e & 7;
            float4 v = *(const float4*)&W[(size_t)(n0 + r) * DM + k0 + j * 4];
            float* d = &sW[r * PLDA + j * 4];
            d[0] = t32f(v.x); d[1] = t32f(v.y); d[2] = t32f(v.z); d[3] = t32f(v.w);
        }
        __syncthreads();
        #pragma unroll
        for (int kk = 0; kk < 32; kk += 8) {
            uint32_t af[2][4];
            #pragma unroll
            for (int mt = 0; mt < 2; mt++) {
                int base = (wm + mt * 16 + g) * PLDA + kk + q4;
                af[mt][0] = fu(sA[base]);
                af[mt][1] = fu(sA[base + 8 * PLDA]);
                af[mt][2] = fu(sA[base + 4]);
                af[mt][3] = fu(sA[base + 8 * PLDA + 4]);
            }
            #pragma unroll
            for (int nt = 0; nt < 4; nt++) {
                int bb = (wn + nt * 8 + g) * PLDA + kk + q4;
                uint32_t b0 = fu(sW[bb]), b1 = fu(sW[bb + 4]);
                mm8(acc[0][nt], af[0], b0, b1);
                mm8(acc[1][nt], af[1], b0, b1);
            }
        }
        __syncthreads();
    }
    #pragma unroll
    for (int mt = 0; mt < 2; mt++)
        #pragma unroll
        for (int nt = 0; nt < 4; nt++) {
            int r0 = m0 + wm + mt * 16 + g;
            int col = n0 + wn + nt * 8 + 2 * q4;
            float* a = acc[mt][nt];
            C[(size_t)r0 * DM + col]           = a[0];
            C[(size_t)r0 * DM + col + 1]       = a[1];
            C[(size_t)(r0 + 8) * DM + col]     = a[2];
            C[(size_t)(r0 + 8) * DM + col + 1] = a[3];
        }
}

__global__ void __launch_bounds__(256, 1)
qkv_proj(const float* __restrict__ x, const float* __restrict__ Wq,
         const float* __restrict__ Wk, const float* __restrict__ Wv) {
    if (blockIdx.z == 0)      proj_body(x, Wq, g_q);
    else if (blockIdx.z == 1) proj_body(x, Wk, g_k);
    else                      proj_body(x, Wv, g_v);
}

__global__ void __launch_bounds__(256, 1)
out_proj(const float* __restrict__ Wo, float* __restrict__ out) {
    proj_body(g_ctx, Wo, out);
}

// ---------- split Q (scaled) and K into packed bf16 hi/lo ----------
__global__ void __launch_bounds__(256, 1) split_qk() {
    const float scale = 0.04419417382415922f;  // 1/sqrt(512)
    size_t i4 = ((size_t)blockIdx.x * 256 + threadIdx.x) * 4;
    float4 q = *(const float4*)(g_q + i4);
    uint32_t h0, l0, h1, l1;
    sp2b(q.x * scale, q.y * scale, h0, l0);
    sp2b(q.z * scale, q.w * scale, h1, l1);
    *(uint2*)(g_qh + i4) = make_uint2(h0, h1);
    *(uint2*)(g_ql + i4) = make_uint2(l0, l1);
    float4 k = *(const float4*)(g_k + i4);
    sp2b(k.x, k.y, h0, l0);
    sp2b(k.z, k.w, h1, l1);
    *(uint2*)(g_kh + i4) = make_uint2(h0, h1);
    *(uint2*)(g_kl + i4) = make_uint2(l0, l1);
}

// ---------- V transpose + split: g_v[b][s][d] -> g_vth/l[b][d][s] ----------
__global__ void __launch_bounds__(256, 1) vtrans() {
    __shared__ float tile[32][33];
    const int s0 = blockIdx.x * 32, d0 = blockIdx.y * 32, b = blockIdx.z;
    const int tx = threadIdx.x & 31, ty = threadIdx.x >> 5;
    #pragma unroll
    for (int j = 0; j < 4; j++) {
        int rr = ty + j * 8;
        tile[rr][tx] = g_v[((size_t)b * SEQ + s0 + rr) * DM + d0 + tx];
    }
    __syncthreads();
    #pragma unroll
    for (int j = 0; j < 4; j++) {
        int rr = ty + j * 8;
        float v = tile[tx][rr];
        uint32_t rh = bfr(v);
        float lo = v - __uint_as_float(rh);
        size_t o = ((size_t)b * DM + d0 + rr) * SEQ + s0 + tx;
        g_vth[o] = (uint16_t)(rh >> 16);
        g_vtl[o] = (uint16_t)(bfr(lo) >> 16);
    }
}

// ======== split-bf16 MMA flash attention: q-tile 32, k-tile 128, 256 thr ========
// word offsets into dynamic smem (uint32 units)
#define LQW 260          // Q row stride in words (520 bf16)
#define LKW 68           // K/V/P row stride in words (136 bf16)
#define OQH 0            // 32*260 = 8320
#define OQL 8320
#define OKH 16640        // 128*68 = 8704
#define OKL 25344
#define OS  34048        // fp32 scores 32*132 = 4224
#define OPH 38272        // 32*68 = 2176
#define OPL 40448
#define OA  42624
#define OL  42656
#define A_WORDS 42688
#define A_BYTES (A_WORDS*4)

__global__ void __launch_bounds__(256, 1) attn() {
    extern __shared__ uint32_t sh[];
    float* sS = (float*)(sh + OS);
    float* sAlp = (float*)(sh + OA);
    float* sL = (float*)(sh + OL);
    const int t = threadIdx.x, w = t >> 5, lane = t & 31;
    const int g = lane >> 2, q4 = lane & 3;
    const int qt = 127 - blockIdx.x, b = blockIdx.y;   // longest-first
    const int q0 = qt * 32;
    const int mq = (w & 1) * 16;      // warp's 16 q-rows
    const int wn = (w >> 1) * 32;     // warp's 32-col group
    const int row = t >> 3, sub = t & 7;
    const int ktmax = (q0 + 31) >> 7;

    // stage full Q tile (hi/lo packed bf16) once
    {
        const uint4* Qh4 = (const uint4*)(g_qh + ((size_t)b * SEQ + q0) * DM);
        const uint4* Ql4 = (const uint4*)(g_ql + ((size_t)b * SEQ + q0) * DM);
        #pragma unroll
        for (int i = 0; i < 8; i++) {
            int e = t + i * 256, r = e >> 6, j = e & 63;   // 64 uint4 per row
            *(uint4*)(sh + OQH + r * LQW + j * 4) = Qh4[r * 64 + j];
            *(uint4*)(sh + OQL + r * LQW + j * 4) = Ql4[r * 64 + j];
        }
    }
    float oacc[4][4][4];
    #pragma unroll
    for (int c = 0; c < 4; c++)
        #pragma unroll
        for (int nt = 0; nt < 4; nt++)
            #pragma unroll
            for (int i = 0; i < 4; i++) oacc[c][nt][i] = 0.f;
    float m_run = -INFINITY, l_run = 0.f;
    __syncthreads();

    for (int kt = 0; kt <= ktmax; kt++) {
        const int k0 = kt * 128;
        float sacc[4][4];
        #pragma unroll
        for (int nt = 0; nt < 4; nt++)
            #pragma unroll
            for (int i = 0; i < 4; i++) sacc[nt][i] = 0.f;

        // ---- S = Q K^T over 4 d-chunks ----
        for (int c = 0; c < 4; c++) {
            const uint4* Kh4 = (const uint4*)(g_kh + ((size_t)b * SEQ + k0) * DM + c * 128);
            const uint4* Kl4 = (const uint4*)(g_kl + ((size_t)b * SEQ + k0) * DM + c * 128);
            #pragma unroll
            for (int i = 0; i < 8; i++) {
                int e = t + i * 256, r = e >> 4, j = e & 15;   // 16 uint4 per row
                *(uint4*)(sh + OKH + r * LKW + j * 4) = Kh4[r * 64 + j];
                *(uint4*)(sh + OKL + r * LKW + j * 4) = Kl4[r * 64 + j];
            }
            __syncthreads();
            #pragma unroll
            for (int kk = 0; kk < 128; kk += 16) {
                int ab = (mq + g) * LQW + ((c * 128 + kk) >> 1) + q4;
                uint32_t ah[4] = { sh[OQH + ab], sh[OQH + ab + 8 * LQW],
                                   sh[OQH + ab + 4], sh[OQH + ab + 8 * LQW + 4] };
                uint32_t al[4] = { sh[OQL + ab], sh[OQL + ab + 8 * LQW],
                                   sh[OQL + ab + 4], sh[OQL + ab + 8 * LQW + 4] };
                #pragma unroll
                for (int nt = 0; nt < 4; nt++) {
                    int bb = (wn + nt * 8 + g) * LKW + (kk >> 1) + q4;
                    uint32_t bh0 = sh[OKH + bb], bh1 = sh[OKH + bb + 4];
                    uint32_t bl0 = sh[OKL + bb], bl1 = sh[OKL + bb + 4];
                    mm16(sacc[nt], ah, bh0, bh1);
                    mm16(sacc[nt], ah, bl0, bl1);
                    mm16(sacc[nt], al, bh0, bh1);
                }
            }
            __syncthreads();
        }
        // ---- S -> smem ----
        #pragma unroll
        for (int nt = 0; nt < 4; nt++) {
            int r0 = mq + g, col = wn + nt * 8 + 2 * q4;
            sS[r0 * 132 + col]           = sacc[nt][0];
            sS[r0 * 132 + col + 1]       = sacc[nt][1];
            sS[(r0 + 8) * 132 + col]     = sacc[nt][2];
            sS[(r0 + 8) * 132 + col + 1] = sacc[nt][3];
        }
        __syncthreads();
        // ---- online softmax: 8 threads/row, 16 keys each ----
        float sv[16], mx = -INFINITY;
        const bool lastt = (kt == ktmax);
        #pragma unroll
        for (int i = 0; i < 16; i++) {
            float s = sS[row * 132 + sub * 16 + i];
            if (lastt && (k0 + sub * 16 + i > q0 + row)) s = -INFINITY;
            sv[i] = s;
            mx = fmaxf(mx, s);
        }
        #pragma unroll
        for (int o = 1; o < 8; o <<= 1) mx = fmaxf(mx, __shfl_xor_sync(~0u, mx, o));
        float mnew = fmaxf(m_run, mx);
        float alpha = __expf(m_run - mnew);
        float ps = 0.f;
        #pragma unroll
        for (int i = 0; i < 16; i++) { sv[i] = __expf(sv[i] - mnew); ps += sv[i]; }
        #pragma unroll
        for (int o = 1; o < 8; o <<= 1) ps += __shfl_xor_sync(~0u, ps, o);
        l_run = l_run * alpha + ps;
        m_run = mnew;
        if (sub == 0) sAlp[row] = alpha;
        #pragma unroll
        for (int i = 0; i < 16; i += 2) {                 // P -> packed bf16 hi/lo
            uint32_t h, l;
            sp2b(sv[i], sv[i + 1], h, l);
            sh[OPH + row * LKW + sub * 8 + (i >> 1)] = h;
            sh[OPL + row * LKW + sub * 8 + (i >> 1)] = l;
        }
        __syncthreads();
        // ---- rescale O ----
        {
            float a0 = sAlp[mq + g], a1 = sAlp[mq + g + 8];
            #pragma unroll
            for (int c = 0; c < 4; c++)
                #pragma unroll
                for (int nt = 0; nt < 4; nt++) {
                    oacc[c][nt][0] *= a0; oacc[c][nt][1] *= a0;
                    oacc[c][nt][2] *= a1; oacc[c][nt][3] *= a1;
                }
        }
        // ---- O += P V over 4 d-chunks (V^T tiles reuse K buffers) ----
        for (int c = 0; c < 4; c++) {
            const uint4* Vh4 = (const uint4*)(g_vth + ((size_t)b * DM + c * 128) * SEQ + k0);
            const uint4* Vl4 = (const uint4*)(g_vtl + ((size_t)b * DM + c * 128) * SEQ + k0);
            #pragma unroll
            for (int i = 0; i < 8; i++) {
                int e = t + i * 256, r = e >> 4, j = e & 15;  // row=d-local, 16 uint4/row
                *(uint4*)(sh + OKH + r * LKW + j * 4) = Vh4[r * 512 + j];
                *(uint4*)(sh + OKL + r * LKW + j * 4) = Vl4[r * 512 + j];
            }
            __syncthreads();
            #pragma unroll
            for (int kk = 0; kk < 128; kk += 16) {
                int ab = (mq + g) * LKW + (kk >> 1) + q4;
                uint32_t ph[4] = { sh[OPH + ab], sh[OPH + ab + 8 * LKW],
                                   sh[OPH + ab + 4], sh[OPH + ab + 8 * LKW + 4] };
                uint32_t pl[4] = { sh[OPL + ab], sh[OPL + ab + 8 * LKW],
                                   sh[OPL + ab + 4], sh[OPL + ab + 8 * LKW + 4] };
                #pragma unroll
                for (int nt = 0; nt < 4; nt++) {
                    int bb = (wn + nt * 8 + g) * LKW + (kk >> 1) + q4;   // row = d
                    uint32_t vh0 = sh[OKH + bb], vh1 = sh[OKH + bb + 4];
                    uint32_t vl0 = sh[OKL + bb], vl1 = sh[OKL + bb + 4];
                    mm16(oacc[c][nt], ph, vh0, vh1);
                    mm16(oacc[c][nt], ph, vl0, vl1);
                    mm16(oacc[c][nt], pl, vh0, vh1);
                }
            }
            __syncthreads();
        }
    }
    // ---- epilogue ----
    if (sub == 0) sL[row] = l_run;
    __syncthreads();
    {
        float li0 = 1.f / sL[mq + g], li1 = 1.f / sL[mq + g + 8];
        #pragma unroll
        for (int c = 0; c < 4; c++)
            #pragma unroll
            for (int nt = 0; nt < 4; nt++) {
                int col = c * 128 + wn + nt * 8 + 2 * q4;
                size_t r0 = ((size_t)b * SEQ + q0 + mq + g) * DM;
                float* a = oacc[c][nt];
                g_ctx[r0 + col]              = a[0] * li0;
                g_ctx[r0 + col + 1]          = a[1] * li0;
                g_ctx[r0 + 8 * DM + col]     = a[2] * li1;
                g_ctx[r0 + 8 * DM + col + 1] = a[3] * li1;
            }
    }
}

extern "C" void kernel_launch(void* const* d_in, const int* in_sizes, int n_in,
                              void* d_out, int out_size) {
    (void)in_sizes; (void)n_in; (void)out_size;
    const float* x  = (const float*)d_in[0];
    const float* Wq = (const float*)d_in[1];
    const float* Wk = (const float*)d_in[2];
    const float* Wv = (const float*)d_in[3];
    const float* Wo = (const float*)d_in[4];
    float* out = (float*)d_out;

    qkv_proj<<<dim3(8, 128, 3), 256>>>(x, Wq, Wk, Wv);
    split_qk<<<MROWS * DM / 4 / 256, 256>>>();
    vtrans<<<dim3(SEQ / 32, DM / 32, BATCH), 256>>>();

    cudaFuncSetAttribute(attn, cudaFuncAttributeMaxDynamicSharedMemorySize, A_BYTES);
    attn<<<dim3(128, BATCH), 256, A_BYTES>>>();

    out_proj<<<dim3(8, 128), 256>>>(Wo, out);
}